// round 14
// baseline (speedup 1.0000x reference)
#include <cuda_runtime.h>
#include <cstdint>
#include <cstddef>

#define BATCH 32
#define NNODE 1024
#define FIN   128
#define HID1  64
#define HID2  32
#define OUTD  10
#define MAXDEG 96      // Binomial(1024,0.01): P(deg>96) ~ 1e-80
#define SROWS 8        // rows per scan block (4096 blocks)
#define NBLK2 32       // 32-node blocks for layer kernels (1024 blocks)

typedef unsigned long long u64;

// ---------------- device scratch ----------------
__device__ int   g_deg[BATCH * NNODE];
__device__ int   g_nbr[(size_t)BATCH * NNODE * MAXDEG];   // values always in [0,1023]
__device__ float g_y1 [(size_t)BATCH * NNODE * HID1];
__device__ float g_y2 [(size_t)BATCH * NNODE * HID2];
__device__ float g_bmax[BATCH * NBLK2 * HID2];
__device__ unsigned g_ctr = 0;   // re-zeroed by last block each run -> replay-safe

// ---------------- f32x2 helpers ----------------
__device__ __forceinline__ void ffma2(u64 &d, u64 a, u64 b) {
    asm("fma.rn.f32x2 %0, %1, %2, %0;" : "+l"(d) : "l"(a), "l"(b));
}
__device__ __forceinline__ void fadd2(u64 &d, u64 s) {
    asm("add.rn.f32x2 %0, %0, %1;" : "+l"(d) : "l"(s));
}
__device__ __forceinline__ u64 pack2(float lo, float hi) {
    u64 r; asm("mov.b64 %0, {%1, %2};" : "=l"(r) : "f"(lo), "f"(hi)); return r;
}
__device__ __forceinline__ void unpack2(u64 v, float &lo, float &hi) {
    asm("mov.b64 {%0, %1}, %2;" : "=f"(lo), "=f"(hi) : "l"(v));
}
__device__ __forceinline__ float hsum2(u64 v) {
    float lo, hi; unpack2(v, lo, hi); return lo + hi;
}
__device__ __forceinline__ u64 sel0(u64 v, bool c) { return c ? v : 0ULL; }
__device__ __forceinline__ float self0(float v, bool c) { return c ? v : 0.f; }

// warp-wide bitonic sort of 32 keys (one per lane), ascending
__device__ __forceinline__ int bitonic32(int key, int l) {
    #pragma unroll
    for (int k = 2; k <= 32; k <<= 1) {
        #pragma unroll
        for (int j = k >> 1; j > 0; j >>= 1) {
            int partner = __shfl_xor_sync(0xffffffffu, key, j);
            bool up = ((l & k) == 0);
            bool takeMin = (((l & j) == 0) == up);
            key = takeMin ? min(key, partner) : max(key, partner);
        }
    }
    return key;
}

// =====================================================================
// K-scan: 8 rows/block (4096 blocks), front-batched LDG.128,
//         warp-parallel bitonic sort (1 row/warp).
// =====================================================================
__global__ void __launch_bounds__(256, 8)
gin_scan(const float* __restrict__ adj)
{
    __shared__ int sIdx[SROWS * MAXDEG];
    __shared__ int sCnt[SROWS];

    const int tid   = threadIdx.x;
    const int b     = blockIdx.x >> 7;              // 128 scan blocks per graph
    const int nbase = (blockIdx.x & 127) * SROWS;
    const size_t boff = (size_t)b * NNODE;

    if (tid < SROWS) sCnt[tid] = 0;
    __syncthreads();

    const int cbase = tid * 4;
    const uint4* arow = (const uint4*)(adj + (boff + nbase) * NNODE) + tid;

    {
        uint4 v[8];
        #pragma unroll
        for (int i = 0; i < 8; ++i)                 // 8 independent LDG.128
            v[i] = __ldcs(arow + (size_t)i * (NNODE/4));
        #pragma unroll
        for (int i = 0; i < 8; ++i) {
            if (v[i].x | v[i].y | v[i].z | v[i].w) {   // ~15% hit per uint4
                if (v[i].x) { int p = atomicAdd(&sCnt[i], 1); if (p < MAXDEG) sIdx[i*MAXDEG + p] = cbase;     }
                if (v[i].y) { int p = atomicAdd(&sCnt[i], 1); if (p < MAXDEG) sIdx[i*MAXDEG + p] = cbase + 1; }
                if (v[i].z) { int p = atomicAdd(&sCnt[i], 1); if (p < MAXDEG) sIdx[i*MAXDEG + p] = cbase + 2; }
                if (v[i].w) { int p = atomicAdd(&sCnt[i], 1); if (p < MAXDEG) sIdx[i*MAXDEG + p] = cbase + 3; }
            }
        }
    }
    __syncthreads();

    const int w = tid >> 5;                         // 1 row per warp
    const int l = tid & 31;
    const size_t node = boff + nbase + w;
    int* idx = sIdx + w * MAXDEG;
    const int deg = min(sCnt[w], MAXDEG);

    if (deg <= 32) {
        int key = (l < deg) ? idx[l] : 0x7fffffff;
        key = bitonic32(key, l);
        if (l < deg) g_nbr[node*MAXDEG + l] = key;
    } else {
        if (l == 0) {
            for (int i = 1; i < deg; ++i) {
                int kk = idx[i], j = i - 1;
                while (j >= 0 && idx[j] > kk) { idx[j+1] = idx[j]; --j; }
                idx[j+1] = kk;
            }
        }
        __syncwarp();
        for (int kk = l; kk < deg; kk += 32) g_nbr[node*MAXDEG + kk] = idx[kk];
    }
    if (l == 0) g_deg[node] = deg;
}

// =====================================================================
// K-ygemm: Y1 = x @ W1a  (unchanged)
// =====================================================================
#define YG_SMEM (8192 * 4)

__global__ void __launch_bounds__(256, 3)
gin_ygemm(const float* __restrict__ x, const float* __restrict__ W1a)
{
    extern __shared__ float Wq[];
    const int tid = threadIdx.x;
    const int m0  = blockIdx.x * 64;

    for (int i = tid; i < 8192; i += 256) {
        int f = i >> 6, c = i & 63;
        Wq[(f >> 2)*256 + c*4 + (f & 3)] = W1a[i];
    }
    __syncthreads();

    const int tc = tid & 15, tr = tid >> 4;
    const int n0 = tr * 4;

    const ulonglong2* x0 = (const ulonglong2*)(x + (size_t)(m0 + n0    ) * FIN);
    const ulonglong2* x1 = (const ulonglong2*)(x + (size_t)(m0 + n0 + 1) * FIN);
    const ulonglong2* x2 = (const ulonglong2*)(x + (size_t)(m0 + n0 + 2) * FIN);
    const ulonglong2* x3 = (const ulonglong2*)(x + (size_t)(m0 + n0 + 3) * FIN);

    u64 acc[4][4];
    #pragma unroll
    for (int r = 0; r < 4; ++r)
        #pragma unroll
        for (int cc = 0; cc < 4; ++cc) acc[r][cc] = 0;

    #pragma unroll 4
    for (int q = 0; q < 32; ++q) {
        ulonglong2 z0 = __ldg(x0 + q);
        ulonglong2 z1 = __ldg(x1 + q);
        ulonglong2 z2 = __ldg(x2 + q);
        ulonglong2 z3 = __ldg(x3 + q);
        const float* wb = Wq + q*256;
        ulonglong2 w0 = *(const ulonglong2*)(wb + (tc     )*4);
        ulonglong2 w1 = *(const ulonglong2*)(wb + (tc + 16)*4);
        ulonglong2 w2 = *(const ulonglong2*)(wb + (tc + 32)*4);
        ulonglong2 w3 = *(const ulonglong2*)(wb + (tc + 48)*4);
        ffma2(acc[0][0], z0.x, w0.x); ffma2(acc[0][0], z0.y, w0.y);
        ffma2(acc[0][1], z0.x, w1.x); ffma2(acc[0][1], z0.y, w1.y);
        ffma2(acc[0][2], z0.x, w2.x); ffma2(acc[0][2], z0.y, w2.y);
        ffma2(acc[0][3], z0.x, w3.x); ffma2(acc[0][3], z0.y, w3.y);
        ffma2(acc[1][0], z1.x, w0.x); ffma2(acc[1][0], z1.y, w0.y);
        ffma2(acc[1][1], z1.x, w1.x); ffma2(acc[1][1], z1.y, w1.y);
        ffma2(acc[1][2], z1.x, w2.x); ffma2(acc[1][2], z1.y, w2.y);
        ffma2(acc[1][3], z1.x, w3.x); ffma2(acc[1][3], z1.y, w3.y);
        ffma2(acc[2][0], z2.x, w0.x); ffma2(acc[2][0], z2.y, w0.y);
        ffma2(acc[2][1], z2.x, w1.x); ffma2(acc[2][1], z2.y, w1.y);
        ffma2(acc[2][2], z2.x, w2.x); ffma2(acc[2][2], z2.y, w2.y);
        ffma2(acc[2][3], z2.x, w3.x); ffma2(acc[2][3], z2.y, w3.y);
        ffma2(acc[3][0], z3.x, w0.x); ffma2(acc[3][0], z3.y, w0.y);
        ffma2(acc[3][1], z3.x, w1.x); ffma2(acc[3][1], z3.y, w1.y);
        ffma2(acc[3][2], z3.x, w2.x); ffma2(acc[3][2], z3.y, w2.y);
        ffma2(acc[3][3], z3.x, w3.x); ffma2(acc[3][3], z3.y, w3.y);
    }
    #pragma unroll
    for (int r = 0; r < 4; ++r)
        #pragma unroll
        for (int cc = 0; cc < 4; ++cc)
            g_y1[(size_t)(m0 + n0 + r)*HID1 + tc + 16*cc] = hsum2(acc[r][cc]);
}

// =====================================================================
// K-layer1: pipelined-index gather(Y1)+b1a+relu -> @W2a(+b2a)*mask -> @W1b
// grid = 1024 (32 nodes/block), 256 threads
// =====================================================================
#define L1_ZS   0
#define L1_W2   (L1_ZS + 32*68)
#define L1_W1B  (L1_W2 + 4096)
#define L1_HS   (L1_W1B + 2048)
#define L1_MSK  (L1_HS + 32*68)
#define L1_FLOATS (L1_MSK + 32)
#define L1_SMEM (L1_FLOATS * 4)

__global__ void __launch_bounds__(256, 4)
gin_layer1(const float* __restrict__ mask,
           const float* __restrict__ b1a,
           const float* __restrict__ W2a, const float* __restrict__ b2a,
           const float* __restrict__ W1b)
{
    extern __shared__ float sm[];
    float* Zs  = sm + L1_ZS;
    float* W2q = sm + L1_W2;
    float* W1q = sm + L1_W1B;
    float* Hs  = sm + L1_HS;
    float* msk = sm + L1_MSK;

    const int tid   = threadIdx.x;
    const int b     = blockIdx.x >> 5;
    const int nbase = (blockIdx.x & 31) * 32;
    const size_t boff = (size_t)b * NNODE;

    for (int i = tid; i < 4096; i += 256) {
        int f = i >> 6, c = i & 63;
        W2q[(f >> 2)*256 + c*4 + (f & 3)] = W2a[i];
    }
    for (int i = tid; i < 2048; i += 256) {
        int f = i >> 5, c = i & 31;
        W1q[(f >> 2)*128 + c*4 + (f & 3)] = W1b[i];
    }
    if (tid < 32) msk[tid] = mask[b*NNODE + nbase + tid];

    const int w = tid >> 5;
    const int l = tid & 31;
    const float blo = b1a[2*l], bhi = b1a[2*l + 1];
    const float* y1b = g_y1 + boff * HID1 + 2*l;

    int cur_deg;
    int4 i0, i1, i2, i3;
    {
        const size_t node0 = boff + nbase + w;
        cur_deg = g_deg[node0];
        const int4* nb4 = (const int4*)(g_nbr + node0*MAXDEG);
        i0 = nb4[0]; i1 = nb4[1]; i2 = nb4[2]; i3 = nb4[3];
    }

    #pragma unroll
    for (int it = 0; it < 4; ++it) {
        const int r = w + it * 8;
        const size_t node = boff + nbase + r;
        const int deg = cur_deg;
        const int* nb = g_nbr + node*MAXDEG;

        u64 a0 = *(const u64*)(g_y1 + node*HID1 + 2*l);
        u64 a1 = 0, a2 = 0, a3 = 0;

        u64 v0  = *(const u64*)(y1b + (i0.x << 6));
        u64 v1  = *(const u64*)(y1b + (i0.y << 6));
        u64 v2  = *(const u64*)(y1b + (i0.z << 6));
        u64 v3  = *(const u64*)(y1b + (i0.w << 6));
        u64 v4  = *(const u64*)(y1b + (i1.x << 6));
        u64 v5  = *(const u64*)(y1b + (i1.y << 6));
        u64 v6  = *(const u64*)(y1b + (i1.z << 6));
        u64 v7  = *(const u64*)(y1b + (i1.w << 6));
        u64 v8  = *(const u64*)(y1b + (i2.x << 6));
        u64 v9  = *(const u64*)(y1b + (i2.y << 6));
        u64 v10 = *(const u64*)(y1b + (i2.z << 6));
        u64 v11 = *(const u64*)(y1b + (i2.w << 6));
        u64 v12 = *(const u64*)(y1b + (i3.x << 6));
        u64 v13 = *(const u64*)(y1b + (i3.y << 6));
        u64 v14 = *(const u64*)(y1b + (i3.z << 6));
        u64 v15 = *(const u64*)(y1b + (i3.w << 6));

        if (it < 3) {
            const size_t noden = boff + nbase + r + 8;
            cur_deg = g_deg[noden];
            const int4* nb4n = (const int4*)(g_nbr + noden*MAXDEG);
            i0 = nb4n[0]; i1 = nb4n[1]; i2 = nb4n[2]; i3 = nb4n[3];
        }

        fadd2(a0, sel0(v0,  0 < deg)); fadd2(a1, sel0(v1,  1 < deg));
        fadd2(a2, sel0(v2,  2 < deg)); fadd2(a3, sel0(v3,  3 < deg));
        fadd2(a0, sel0(v4,  4 < deg)); fadd2(a1, sel0(v5,  5 < deg));
        fadd2(a2, sel0(v6,  6 < deg)); fadd2(a3, sel0(v7,  7 < deg));
        fadd2(a0, sel0(v8,  8 < deg)); fadd2(a1, sel0(v9,  9 < deg));
        fadd2(a2, sel0(v10, 10 < deg)); fadd2(a3, sel0(v11, 11 < deg));
        fadd2(a0, sel0(v12, 12 < deg)); fadd2(a1, sel0(v13, 13 < deg));
        fadd2(a2, sel0(v14, 14 < deg)); fadd2(a3, sel0(v15, 15 < deg));

        for (int k = 16; k < deg; ++k)                 // P(deg>16) ~ 2%
            fadd2(a0, *(const u64*)(y1b + (nb[k] << 6)));

        fadd2(a0, a1); fadd2(a2, a3); fadd2(a0, a2);
        float lo, hi; unpack2(a0, lo, hi);
        lo = fmaxf(lo + blo, 0.f); hi = fmaxf(hi + bhi, 0.f);
        *(u64*)(Zs + r*68 + 2*l) = pack2(lo, hi);
    }
    __syncthreads();

    const int tc = tid & 15, tr = tid >> 4;
    const int n0 = tr * 2;

    u64 acc[2][4];
    #pragma unroll
    for (int cc = 0; cc < 4; ++cc) {
        u64 ini = pack2(b2a[tc + 16*cc], 0.f);
        acc[0][cc] = ini; acc[1][cc] = ini;
    }
    #pragma unroll 2
    for (int f = 0; f < 64; f += 4) {
        ulonglong2 z0 = *(const ulonglong2*)(Zs + (n0+0)*68 + f);
        ulonglong2 z1 = *(const ulonglong2*)(Zs + (n0+1)*68 + f);
        const float* wb = W2q + (f >> 2)*256;
        ulonglong2 w0 = *(const ulonglong2*)(wb + (tc     )*4);
        ulonglong2 w1 = *(const ulonglong2*)(wb + (tc + 16)*4);
        ulonglong2 w2 = *(const ulonglong2*)(wb + (tc + 32)*4);
        ulonglong2 w3 = *(const ulonglong2*)(wb + (tc + 48)*4);
        ffma2(acc[0][0], z0.x, w0.x); ffma2(acc[0][0], z0.y, w0.y);
        ffma2(acc[0][1], z0.x, w1.x); ffma2(acc[0][1], z0.y, w1.y);
        ffma2(acc[0][2], z0.x, w2.x); ffma2(acc[0][2], z0.y, w2.y);
        ffma2(acc[0][3], z0.x, w3.x); ffma2(acc[0][3], z0.y, w3.y);
        ffma2(acc[1][0], z1.x, w0.x); ffma2(acc[1][0], z1.y, w0.y);
        ffma2(acc[1][1], z1.x, w1.x); ffma2(acc[1][1], z1.y, w1.y);
        ffma2(acc[1][2], z1.x, w2.x); ffma2(acc[1][2], z1.y, w2.y);
        ffma2(acc[1][3], z1.x, w3.x); ffma2(acc[1][3], z1.y, w3.y);
    }
    #pragma unroll
    for (int r = 0; r < 2; ++r) {
        const float m = msk[n0 + r];
        #pragma unroll
        for (int cc = 0; cc < 4; ++cc)
            Hs[(n0+r)*68 + tc + 16*cc] = hsum2(acc[r][cc]) * m;
    }
    __syncthreads();

    u64 acc3[2][2];
    acc3[0][0] = 0; acc3[0][1] = 0; acc3[1][0] = 0; acc3[1][1] = 0;
    #pragma unroll 2
    for (int f = 0; f < 64; f += 4) {
        ulonglong2 z0 = *(const ulonglong2*)(Hs + (n0+0)*68 + f);
        ulonglong2 z1 = *(const ulonglong2*)(Hs + (n0+1)*68 + f);
        const float* wb = W1q + (f >> 2)*128;
        ulonglong2 w0 = *(const ulonglong2*)(wb + (tc     )*4);
        ulonglong2 w1 = *(const ulonglong2*)(wb + (tc + 16)*4);
        ffma2(acc3[0][0], z0.x, w0.x); ffma2(acc3[0][0], z0.y, w0.y);
        ffma2(acc3[0][1], z0.x, w1.x); ffma2(acc3[0][1], z0.y, w1.y);
        ffma2(acc3[1][0], z1.x, w0.x); ffma2(acc3[1][0], z1.y, w0.y);
        ffma2(acc3[1][1], z1.x, w1.x); ffma2(acc3[1][1], z1.y, w1.y);
    }
    #pragma unroll
    for (int r = 0; r < 2; ++r) {
        const size_t node = boff + nbase + n0 + r;
        g_y2[node*HID2 + tc     ] = hsum2(acc3[r][0]);
        g_y2[node*HID2 + tc + 16] = hsum2(acc3[r][1]);
    }
}

// =====================================================================
// K-layer2out: pipelined-index gather(Y2)+b1b+relu -> @W2b(+b2b)*mask
//              -> blockmax -> last-block FC
// =====================================================================
__global__ void __launch_bounds__(256, 6)
gin_layer2out(const float* __restrict__ mask,
              const float* __restrict__ b1b,
              const float* __restrict__ W2b, const float* __restrict__ b2b,
              const float* __restrict__ Wfc, const float* __restrict__ bfc,
              float* __restrict__ out)
{
    __shared__ float Zs[32*36];
    __shared__ float W2q[1024];
    __shared__ float Hs[32*33];
    __shared__ float msk[32];
    __shared__ bool  sLast;

    const int tid   = threadIdx.x;
    const int b     = blockIdx.x >> 5;
    const int blk   = blockIdx.x & 31;
    const int nbase = blk * 32;
    const size_t boff = (size_t)b * NNODE;

    for (int i = tid; i < 1024; i += 256) {
        int f = i >> 5, c = i & 31;
        W2q[(f >> 2)*128 + c*4 + (f & 3)] = W2b[i];
    }
    if (tid < 32) msk[tid] = mask[b*NNODE + nbase + tid];

    const int w = tid >> 5;
    const int l = tid & 31;
    const float bl = b1b[l];
    const float* y2b = g_y2 + boff*HID2 + l;

    int cur_deg;
    int4 i0, i1, i2, i3;
    {
        const size_t node0 = boff + nbase + w;
        cur_deg = g_deg[node0];
        const int4* nb4 = (const int4*)(g_nbr + node0*MAXDEG);
        i0 = nb4[0]; i1 = nb4[1]; i2 = nb4[2]; i3 = nb4[3];
    }

    #pragma unroll
    for (int it = 0; it < 4; ++it) {
        const int r = w + it * 8;
        const size_t node = boff + nbase + r;
        const int deg = cur_deg;
        const int* nb = g_nbr + node*MAXDEG;

        float a0 = y2b[(size_t)(nbase + r) << 5];
        float a1 = 0.f, a2 = 0.f, a3 = 0.f;

        float v0  = y2b[i0.x << 5], v1  = y2b[i0.y << 5];
        float v2  = y2b[i0.z << 5], v3  = y2b[i0.w << 5];
        float v4  = y2b[i1.x << 5], v5  = y2b[i1.y << 5];
        float v6  = y2b[i1.z << 5], v7  = y2b[i1.w << 5];
        float v8  = y2b[i2.x << 5], v9  = y2b[i2.y << 5];
        float v10 = y2b[i2.z << 5], v11 = y2b[i2.w << 5];
        float v12 = y2b[i3.x << 5], v13 = y2b[i3.y << 5];
        float v14 = y2b[i3.z << 5], v15 = y2b[i3.w << 5];

        if (it < 3) {
            const size_t noden = boff + nbase + r + 8;
            cur_deg = g_deg[noden];
            const int4* nb4n = (const int4*)(g_nbr + noden*MAXDEG);
            i0 = nb4n[0]; i1 = nb4n[1]; i2 = nb4n[2]; i3 = nb4n[3];
        }

        a0 += self0(v0,  0 < deg);  a1 += self0(v1,  1 < deg);
        a2 += self0(v2,  2 < deg);  a3 += self0(v3,  3 < deg);
        a0 += self0(v4,  4 < deg);  a1 += self0(v5,  5 < deg);
        a2 += self0(v6,  6 < deg);  a3 += self0(v7,  7 < deg);
        a0 += self0(v8,  8 < deg);  a1 += self0(v9,  9 < deg);
        a2 += self0(v10, 10 < deg); a3 += self0(v11, 11 < deg);
        a0 += self0(v12, 12 < deg); a1 += self0(v13, 13 < deg);
        a2 += self0(v14, 14 < deg); a3 += self0(v15, 15 < deg);

        for (int k = 16; k < deg; ++k)
            a0 += y2b[nb[k] << 5];

        Zs[r*36 + l] = fmaxf(((a0 + a1) + (a2 + a3)) + bl, 0.f);
    }
    __syncthreads();

    const int tc = tid & 15, tr = tid >> 4;
    const int n0 = tr * 2;

    u64 acc[2][2];
    #pragma unroll
    for (int cc = 0; cc < 2; ++cc) {
        u64 ini = pack2(b2b[tc + 16*cc], 0.f);
        acc[0][cc] = ini; acc[1][cc] = ini;
    }
    #pragma unroll
    for (int f = 0; f < 32; f += 4) {
        ulonglong2 z0 = *(const ulonglong2*)(Zs + (n0+0)*36 + f);
        ulonglong2 z1 = *(const ulonglong2*)(Zs + (n0+1)*36 + f);
        const float* wb = W2q + (f >> 2)*128;
        ulonglong2 w0 = *(const ulonglong2*)(wb + (tc     )*4);
        ulonglong2 w1 = *(const ulonglong2*)(wb + (tc + 16)*4);
        ffma2(acc[0][0], z0.x, w0.x); ffma2(acc[0][0], z0.y, w0.y);
        ffma2(acc[0][1], z0.x, w1.x); ffma2(acc[0][1], z0.y, w1.y);
        ffma2(acc[1][0], z1.x, w0.x); ffma2(acc[1][0], z1.y, w0.y);
        ffma2(acc[1][1], z1.x, w1.x); ffma2(acc[1][1], z1.y, w1.y);
    }
    #pragma unroll
    for (int r = 0; r < 2; ++r) {
        const float m = msk[n0 + r];
        Hs[(n0+r)*33 + tc     ] = hsum2(acc[r][0]) * m;
        Hs[(n0+r)*33 + tc + 16] = hsum2(acc[r][1]) * m;
    }
    __syncthreads();

    if (tid < HID2) {
        float mx = Hs[tid];
        #pragma unroll 8
        for (int n = 1; n < 32; ++n) mx = fmaxf(mx, Hs[n*33 + tid]);
        g_bmax[(b*NBLK2 + blk)*HID2 + tid] = mx;
    }

    __threadfence();
    __syncthreads();
    if (tid == 0) {
        unsigned p = atomicAdd(&g_ctr, 1);
        sLast = (p == gridDim.x - 1);
    }
    __syncthreads();
    if (!sLast) return;
    __threadfence();

    __shared__ float gm[BATCH * HID2];
    for (int it = tid; it < BATCH*HID2; it += 256) {
        const int g = it >> 5, f = it & 31;
        float mx = g_bmax[(g*NBLK2)*HID2 + f];
        #pragma unroll
        for (int k = 1; k < NBLK2; ++k)
            mx = fmaxf(mx, g_bmax[(g*NBLK2 + k)*HID2 + f]);
        gm[it] = mx;
    }
    __syncthreads();
    for (int it = tid; it < BATCH*OUTD; it += 256) {
        const int g = it / OUTD, o = it % OUTD;
        float s = bfc[o];
        #pragma unroll
        for (int c = 0; c < HID2; ++c)
            s += gm[g*HID2 + c] * Wfc[c*OUTD + o];
        out[g*OUTD + o] = s;
    }
    if (tid == 0) g_ctr = 0;
}

// ---------------- launch ----------------
extern "C" void kernel_launch(void* const* d_in, const int* in_sizes, int n_in,
                              void* d_out, int out_size)
{
    const float* x    = (const float*)d_in[0];
    const float* adj  = (const float*)d_in[1];
    const float* mask = (const float*)d_in[2];
    const float* W1a  = (const float*)d_in[3];
    const float* b1a  = (const float*)d_in[4];
    const float* W2a  = (const float*)d_in[5];
    const float* b2a  = (const float*)d_in[6];
    const float* W1b  = (const float*)d_in[7];
    const float* b1b  = (const float*)d_in[8];
    const float* W2b  = (const float*)d_in[9];
    const float* b2b  = (const float*)d_in[10];
    const float* Wfc  = (const float*)d_in[11];
    const float* bfc  = (const float*)d_in[12];
    float* out = (float*)d_out;

    cudaFuncSetAttribute(gin_ygemm,  cudaFuncAttributeMaxDynamicSharedMemorySize, YG_SMEM);
    cudaFuncSetAttribute(gin_layer1, cudaFuncAttributeMaxDynamicSharedMemorySize, L1_SMEM);

    gin_ygemm<<<(BATCH*NNODE)/64, 256, YG_SMEM>>>(x, W1a);
    gin_scan<<<BATCH*(NNODE/SROWS), 256>>>(adj);
    gin_layer1<<<BATCH*NBLK2, 256, L1_SMEM>>>(mask, b1a, W2a, b2a, W1b);
    gin_layer2out<<<BATCH*NBLK2, 256>>>(mask, b1b, W2b, b2b, Wfc, bfc, out);
}

// round 15
// speedup vs baseline: 1.1444x; 1.1444x over previous
#include <cuda_runtime.h>
#include <cstdint>
#include <cstddef>

#define BATCH 32
#define NNODE 1024
#define FIN   128
#define HID1  64
#define HID2  32
#define OUTD  10
#define MAXDEG 96      // Binomial(1024,0.01): P(deg>96) ~ 1e-80
#define SROWS 8        // rows per scan block (4096 blocks)
#define NBLK2 32       // 32-node blocks for layer kernels (1024 blocks)

typedef unsigned long long u64;

// ---------------- device scratch ----------------
__device__ int   g_deg[BATCH * NNODE];
__device__ int   g_nbr[(size_t)BATCH * NNODE * MAXDEG];   // values always in [0,1023]
__device__ float g_y1 [(size_t)BATCH * NNODE * HID1];
__device__ float g_y2 [(size_t)BATCH * NNODE * HID2];
__device__ float g_bmax[BATCH * NBLK2 * HID2];
__device__ unsigned g_ctr = 0;   // re-zeroed by last block each run -> replay-safe

// ---------------- f32x2 helpers ----------------
__device__ __forceinline__ void ffma2(u64 &d, u64 a, u64 b) {
    asm("fma.rn.f32x2 %0, %1, %2, %0;" : "+l"(d) : "l"(a), "l"(b));
}
__device__ __forceinline__ void fadd2(u64 &d, u64 s) {
    asm("add.rn.f32x2 %0, %0, %1;" : "+l"(d) : "l"(s));
}
__device__ __forceinline__ u64 pack2(float lo, float hi) {
    u64 r; asm("mov.b64 %0, {%1, %2};" : "=l"(r) : "f"(lo), "f"(hi)); return r;
}
__device__ __forceinline__ void unpack2(u64 v, float &lo, float &hi) {
    asm("mov.b64 {%0, %1}, %2;" : "=f"(lo), "=f"(hi) : "l"(v));
}
__device__ __forceinline__ float hsum2(u64 v) {
    float lo, hi; unpack2(v, lo, hi); return lo + hi;
}
__device__ __forceinline__ u64 sel0(u64 v, bool c) { return c ? v : 0ULL; }
__device__ __forceinline__ float self0(float v, bool c) { return c ? v : 0.f; }

// warp-wide bitonic sort of 32 keys (one per lane), ascending
__device__ __forceinline__ int bitonic32(int key, int l) {
    #pragma unroll
    for (int k = 2; k <= 32; k <<= 1) {
        #pragma unroll
        for (int j = k >> 1; j > 0; j >>= 1) {
            int partner = __shfl_xor_sync(0xffffffffu, key, j);
            bool up = ((l & k) == 0);
            bool takeMin = (((l & j) == 0) == up);
            key = takeMin ? min(key, partner) : max(key, partner);
        }
    }
    return key;
}

// =====================================================================
// K-scan: 8 rows/block (4096 blocks), front-batched LDG.128,
//         warp-parallel bitonic sort (1 row/warp).   [R13 verbatim]
// =====================================================================
__global__ void __launch_bounds__(256)
gin_scan(const float* __restrict__ adj)
{
    __shared__ int sIdx[SROWS * MAXDEG];
    __shared__ int sCnt[SROWS];

    const int tid   = threadIdx.x;
    const int b     = blockIdx.x >> 7;              // 128 scan blocks per graph
    const int nbase = (blockIdx.x & 127) * SROWS;
    const size_t boff = (size_t)b * NNODE;

    if (tid < SROWS) sCnt[tid] = 0;
    __syncthreads();

    const int cbase = tid * 4;
    const uint4* arow = (const uint4*)(adj + (boff + nbase) * NNODE) + tid;

    {
        uint4 v[8];
        #pragma unroll
        for (int i = 0; i < 8; ++i)                 // 8 independent LDG.128
            v[i] = __ldcs(arow + (size_t)i * (NNODE/4));
        #pragma unroll
        for (int i = 0; i < 8; ++i) {
            if (v[i].x | v[i].y | v[i].z | v[i].w) {   // ~15% hit per uint4
                if (v[i].x) { int p = atomicAdd(&sCnt[i], 1); if (p < MAXDEG) sIdx[i*MAXDEG + p] = cbase;     }
                if (v[i].y) { int p = atomicAdd(&sCnt[i], 1); if (p < MAXDEG) sIdx[i*MAXDEG + p] = cbase + 1; }
                if (v[i].z) { int p = atomicAdd(&sCnt[i], 1); if (p < MAXDEG) sIdx[i*MAXDEG + p] = cbase + 2; }
                if (v[i].w) { int p = atomicAdd(&sCnt[i], 1); if (p < MAXDEG) sIdx[i*MAXDEG + p] = cbase + 3; }
            }
        }
    }
    __syncthreads();

    const int w = tid >> 5;                         // 1 row per warp
    const int l = tid & 31;
    const size_t node = boff + nbase + w;
    int* idx = sIdx + w * MAXDEG;
    const int deg = min(sCnt[w], MAXDEG);

    if (deg <= 32) {
        int key = (l < deg) ? idx[l] : 0x7fffffff;
        key = bitonic32(key, l);
        if (l < deg) g_nbr[node*MAXDEG + l] = key;
    } else {
        if (l == 0) {
            for (int i = 1; i < deg; ++i) {
                int kk = idx[i], j = i - 1;
                while (j >= 0 && idx[j] > kk) { idx[j+1] = idx[j]; --j; }
                idx[j+1] = kk;
            }
        }
        __syncwarp();
        for (int kk = l; kk < deg; kk += 32) g_nbr[node*MAXDEG + kk] = idx[kk];
    }
    if (l == 0) g_deg[node] = deg;
}

// =====================================================================
// K-ygemm: Y1 = x @ W1a  [R13 verbatim]
// =====================================================================
#define YG_SMEM (8192 * 4)

__global__ void __launch_bounds__(256, 3)
gin_ygemm(const float* __restrict__ x, const float* __restrict__ W1a)
{
    extern __shared__ float Wq[];
    const int tid = threadIdx.x;
    const int m0  = blockIdx.x * 64;

    for (int i = tid; i < 8192; i += 256) {
        int f = i >> 6, c = i & 63;
        Wq[(f >> 2)*256 + c*4 + (f & 3)] = W1a[i];
    }
    __syncthreads();

    const int tc = tid & 15, tr = tid >> 4;
    const int n0 = tr * 4;

    const ulonglong2* x0 = (const ulonglong2*)(x + (size_t)(m0 + n0    ) * FIN);
    const ulonglong2* x1 = (const ulonglong2*)(x + (size_t)(m0 + n0 + 1) * FIN);
    const ulonglong2* x2 = (const ulonglong2*)(x + (size_t)(m0 + n0 + 2) * FIN);
    const ulonglong2* x3 = (const ulonglong2*)(x + (size_t)(m0 + n0 + 3) * FIN);

    u64 acc[4][4];
    #pragma unroll
    for (int r = 0; r < 4; ++r)
        #pragma unroll
        for (int cc = 0; cc < 4; ++cc) acc[r][cc] = 0;

    #pragma unroll 4
    for (int q = 0; q < 32; ++q) {
        ulonglong2 z0 = __ldg(x0 + q);
        ulonglong2 z1 = __ldg(x1 + q);
        ulonglong2 z2 = __ldg(x2 + q);
        ulonglong2 z3 = __ldg(x3 + q);
        const float* wb = Wq + q*256;
        ulonglong2 w0 = *(const ulonglong2*)(wb + (tc     )*4);
        ulonglong2 w1 = *(const ulonglong2*)(wb + (tc + 16)*4);
        ulonglong2 w2 = *(const ulonglong2*)(wb + (tc + 32)*4);
        ulonglong2 w3 = *(const ulonglong2*)(wb + (tc + 48)*4);
        ffma2(acc[0][0], z0.x, w0.x); ffma2(acc[0][0], z0.y, w0.y);
        ffma2(acc[0][1], z0.x, w1.x); ffma2(acc[0][1], z0.y, w1.y);
        ffma2(acc[0][2], z0.x, w2.x); ffma2(acc[0][2], z0.y, w2.y);
        ffma2(acc[0][3], z0.x, w3.x); ffma2(acc[0][3], z0.y, w3.y);
        ffma2(acc[1][0], z1.x, w0.x); ffma2(acc[1][0], z1.y, w0.y);
        ffma2(acc[1][1], z1.x, w1.x); ffma2(acc[1][1], z1.y, w1.y);
        ffma2(acc[1][2], z1.x, w2.x); ffma2(acc[1][2], z1.y, w2.y);
        ffma2(acc[1][3], z1.x, w3.x); ffma2(acc[1][3], z1.y, w3.y);
        ffma2(acc[2][0], z2.x, w0.x); ffma2(acc[2][0], z2.y, w0.y);
        ffma2(acc[2][1], z2.x, w1.x); ffma2(acc[2][1], z2.y, w1.y);
        ffma2(acc[2][2], z2.x, w2.x); ffma2(acc[2][2], z2.y, w2.y);
        ffma2(acc[2][3], z2.x, w3.x); ffma2(acc[2][3], z2.y, w3.y);
        ffma2(acc[3][0], z3.x, w0.x); ffma2(acc[3][0], z3.y, w0.y);
        ffma2(acc[3][1], z3.x, w1.x); ffma2(acc[3][1], z3.y, w1.y);
        ffma2(acc[3][2], z3.x, w2.x); ffma2(acc[3][2], z3.y, w2.y);
        ffma2(acc[3][3], z3.x, w3.x); ffma2(acc[3][3], z3.y, w3.y);
    }
    #pragma unroll
    for (int r = 0; r < 4; ++r)
        #pragma unroll
        for (int cc = 0; cc < 4; ++cc)
            g_y1[(size_t)(m0 + n0 + r)*HID1 + tc + 16*cc] = hsum2(acc[r][cc]);
}

// =====================================================================
// K-layer1 [R13 verbatim]
// =====================================================================
#define L1_ZS   0
#define L1_W2   (L1_ZS + 32*68)
#define L1_W1B  (L1_W2 + 4096)
#define L1_HS   (L1_W1B + 2048)
#define L1_MSK  (L1_HS + 32*68)
#define L1_FLOATS (L1_MSK + 32)
#define L1_SMEM (L1_FLOATS * 4)

__global__ void __launch_bounds__(256)
gin_layer1(const float* __restrict__ mask,
           const float* __restrict__ b1a,
           const float* __restrict__ W2a, const float* __restrict__ b2a,
           const float* __restrict__ W1b)
{
    extern __shared__ float sm[];
    float* Zs  = sm + L1_ZS;
    float* W2q = sm + L1_W2;
    float* W1q = sm + L1_W1B;
    float* Hs  = sm + L1_HS;
    float* msk = sm + L1_MSK;

    const int tid   = threadIdx.x;
    const int b     = blockIdx.x >> 5;
    const int nbase = (blockIdx.x & 31) * 32;
    const size_t boff = (size_t)b * NNODE;

    for (int i = tid; i < 4096; i += 256) {
        int f = i >> 6, c = i & 63;
        W2q[(f >> 2)*256 + c*4 + (f & 3)] = W2a[i];
    }
    for (int i = tid; i < 2048; i += 256) {
        int f = i >> 5, c = i & 31;
        W1q[(f >> 2)*128 + c*4 + (f & 3)] = W1b[i];
    }
    if (tid < 32) msk[tid] = mask[b*NNODE + nbase + tid];

    const int w = tid >> 5;
    const int l = tid & 31;
    const float blo = b1a[2*l], bhi = b1a[2*l + 1];
    const float* y1b = g_y1 + boff * HID1 + 2*l;

    int cur_deg;
    int4 i0, i1, i2, i3;
    {
        const size_t node0 = boff + nbase + w;
        cur_deg = g_deg[node0];
        const int4* nb4 = (const int4*)(g_nbr + node0*MAXDEG);
        i0 = nb4[0]; i1 = nb4[1]; i2 = nb4[2]; i3 = nb4[3];
    }

    #pragma unroll
    for (int it = 0; it < 4; ++it) {
        const int r = w + it * 8;
        const size_t node = boff + nbase + r;
        const int deg = cur_deg;
        const int* nb = g_nbr + node*MAXDEG;

        u64 a0 = *(const u64*)(g_y1 + node*HID1 + 2*l);
        u64 a1 = 0, a2 = 0, a3 = 0;

        u64 v0  = *(const u64*)(y1b + (i0.x << 6));
        u64 v1  = *(const u64*)(y1b + (i0.y << 6));
        u64 v2  = *(const u64*)(y1b + (i0.z << 6));
        u64 v3  = *(const u64*)(y1b + (i0.w << 6));
        u64 v4  = *(const u64*)(y1b + (i1.x << 6));
        u64 v5  = *(const u64*)(y1b + (i1.y << 6));
        u64 v6  = *(const u64*)(y1b + (i1.z << 6));
        u64 v7  = *(const u64*)(y1b + (i1.w << 6));
        u64 v8  = *(const u64*)(y1b + (i2.x << 6));
        u64 v9  = *(const u64*)(y1b + (i2.y << 6));
        u64 v10 = *(const u64*)(y1b + (i2.z << 6));
        u64 v11 = *(const u64*)(y1b + (i2.w << 6));
        u64 v12 = *(const u64*)(y1b + (i3.x << 6));
        u64 v13 = *(const u64*)(y1b + (i3.y << 6));
        u64 v14 = *(const u64*)(y1b + (i3.z << 6));
        u64 v15 = *(const u64*)(y1b + (i3.w << 6));

        if (it < 3) {
            const size_t noden = boff + nbase + r + 8;
            cur_deg = g_deg[noden];
            const int4* nb4n = (const int4*)(g_nbr + noden*MAXDEG);
            i0 = nb4n[0]; i1 = nb4n[1]; i2 = nb4n[2]; i3 = nb4n[3];
        }

        fadd2(a0, sel0(v0,  0 < deg)); fadd2(a1, sel0(v1,  1 < deg));
        fadd2(a2, sel0(v2,  2 < deg)); fadd2(a3, sel0(v3,  3 < deg));
        fadd2(a0, sel0(v4,  4 < deg)); fadd2(a1, sel0(v5,  5 < deg));
        fadd2(a2, sel0(v6,  6 < deg)); fadd2(a3, sel0(v7,  7 < deg));
        fadd2(a0, sel0(v8,  8 < deg)); fadd2(a1, sel0(v9,  9 < deg));
        fadd2(a2, sel0(v10, 10 < deg)); fadd2(a3, sel0(v11, 11 < deg));
        fadd2(a0, sel0(v12, 12 < deg)); fadd2(a1, sel0(v13, 13 < deg));
        fadd2(a2, sel0(v14, 14 < deg)); fadd2(a3, sel0(v15, 15 < deg));

        for (int k = 16; k < deg; ++k)                 // P(deg>16) ~ 2%
            fadd2(a0, *(const u64*)(y1b + (nb[k] << 6)));

        fadd2(a0, a1); fadd2(a2, a3); fadd2(a0, a2);
        float lo, hi; unpack2(a0, lo, hi);
        lo = fmaxf(lo + blo, 0.f); hi = fmaxf(hi + bhi, 0.f);
        *(u64*)(Zs + r*68 + 2*l) = pack2(lo, hi);
    }
    __syncthreads();

    const int tc = tid & 15, tr = tid >> 4;
    const int n0 = tr * 2;

    u64 acc[2][4];
    #pragma unroll
    for (int cc = 0; cc < 4; ++cc) {
        u64 ini = pack2(b2a[tc + 16*cc], 0.f);
        acc[0][cc] = ini; acc[1][cc] = ini;
    }
    #pragma unroll 2
    for (int f = 0; f < 64; f += 4) {
        ulonglong2 z0 = *(const ulonglong2*)(Zs + (n0+0)*68 + f);
        ulonglong2 z1 = *(const ulonglong2*)(Zs + (n0+1)*68 + f);
        const float* wb = W2q + (f >> 2)*256;
        ulonglong2 w0 = *(const ulonglong2*)(wb + (tc     )*4);
        ulonglong2 w1 = *(const ulonglong2*)(wb + (tc + 16)*4);
        ulonglong2 w2 = *(const ulonglong2*)(wb + (tc + 32)*4);
        ulonglong2 w3 = *(const ulonglong2*)(wb + (tc + 48)*4);
        ffma2(acc[0][0], z0.x, w0.x); ffma2(acc[0][0], z0.y, w0.y);
        ffma2(acc[0][1], z0.x, w1.x); ffma2(acc[0][1], z0.y, w1.y);
        ffma2(acc[0][2], z0.x, w2.x); ffma2(acc[0][2], z0.y, w2.y);
        ffma2(acc[0][3], z0.x, w3.x); ffma2(acc[0][3], z0.y, w3.y);
        ffma2(acc[1][0], z1.x, w0.x); ffma2(acc[1][0], z1.y, w0.y);
        ffma2(acc[1][1], z1.x, w1.x); ffma2(acc[1][1], z1.y, w1.y);
        ffma2(acc[1][2], z1.x, w2.x); ffma2(acc[1][2], z1.y, w2.y);
        ffma2(acc[1][3], z1.x, w3.x); ffma2(acc[1][3], z1.y, w3.y);
    }
    #pragma unroll
    for (int r = 0; r < 2; ++r) {
        const float m = msk[n0 + r];
        #pragma unroll
        for (int cc = 0; cc < 4; ++cc)
            Hs[(n0+r)*68 + tc + 16*cc] = hsum2(acc[r][cc]) * m;
    }
    __syncthreads();

    u64 acc3[2][2];
    acc3[0][0] = 0; acc3[0][1] = 0; acc3[1][0] = 0; acc3[1][1] = 0;
    #pragma unroll 2
    for (int f = 0; f < 64; f += 4) {
        ulonglong2 z0 = *(const ulonglong2*)(Hs + (n0+0)*68 + f);
        ulonglong2 z1 = *(const ulonglong2*)(Hs + (n0+1)*68 + f);
        const float* wb = W1q + (f >> 2)*128;
        ulonglong2 w0 = *(const ulonglong2*)(wb + (tc     )*4);
        ulonglong2 w1 = *(const ulonglong2*)(wb + (tc + 16)*4);
        ffma2(acc3[0][0], z0.x, w0.x); ffma2(acc3[0][0], z0.y, w0.y);
        ffma2(acc3[0][1], z0.x, w1.x); ffma2(acc3[0][1], z0.y, w1.y);
        ffma2(acc3[1][0], z1.x, w0.x); ffma2(acc3[1][0], z1.y, w0.y);
        ffma2(acc3[1][1], z1.x, w1.x); ffma2(acc3[1][1], z1.y, w1.y);
    }
    #pragma unroll
    for (int r = 0; r < 2; ++r) {
        const size_t node = boff + nbase + n0 + r;
        g_y2[node*HID2 + tc     ] = hsum2(acc3[r][0]);
        g_y2[node*HID2 + tc + 16] = hsum2(acc3[r][1]);
    }
}

// =====================================================================
// K-layer2out [R13 verbatim]
// =====================================================================
__global__ void __launch_bounds__(256)
gin_layer2out(const float* __restrict__ mask,
              const float* __restrict__ b1b,
              const float* __restrict__ W2b, const float* __restrict__ b2b,
              const float* __restrict__ Wfc, const float* __restrict__ bfc,
              float* __restrict__ out)
{
    __shared__ float Zs[32*36];
    __shared__ float W2q[1024];
    __shared__ float Hs[32*33];
    __shared__ float msk[32];
    __shared__ bool  sLast;

    const int tid   = threadIdx.x;
    const int b     = blockIdx.x >> 5;
    const int blk   = blockIdx.x & 31;
    const int nbase = blk * 32;
    const size_t boff = (size_t)b * NNODE;

    for (int i = tid; i < 1024; i += 256) {
        int f = i >> 5, c = i & 31;
        W2q[(f >> 2)*128 + c*4 + (f & 3)] = W2b[i];
    }
    if (tid < 32) msk[tid] = mask[b*NNODE + nbase + tid];

    const int w = tid >> 5;
    const int l = tid & 31;
    const float bl = b1b[l];
    const float* y2b = g_y2 + boff*HID2 + l;

    int cur_deg;
    int4 i0, i1, i2, i3;
    {
        const size_t node0 = boff + nbase + w;
        cur_deg = g_deg[node0];
        const int4* nb4 = (const int4*)(g_nbr + node0*MAXDEG);
        i0 = nb4[0]; i1 = nb4[1]; i2 = nb4[2]; i3 = nb4[3];
    }

    #pragma unroll
    for (int it = 0; it < 4; ++it) {
        const int r = w + it * 8;
        const size_t node = boff + nbase + r;
        const int deg = cur_deg;
        const int* nb = g_nbr + node*MAXDEG;

        float a0 = y2b[(size_t)(nbase + r) << 5];
        float a1 = 0.f, a2 = 0.f, a3 = 0.f;

        float v0  = y2b[i0.x << 5], v1  = y2b[i0.y << 5];
        float v2  = y2b[i0.z << 5], v3  = y2b[i0.w << 5];
        float v4  = y2b[i1.x << 5], v5  = y2b[i1.y << 5];
        float v6  = y2b[i1.z << 5], v7  = y2b[i1.w << 5];
        float v8  = y2b[i2.x << 5], v9  = y2b[i2.y << 5];
        float v10 = y2b[i2.z << 5], v11 = y2b[i2.w << 5];
        float v12 = y2b[i3.x << 5], v13 = y2b[i3.y << 5];
        float v14 = y2b[i3.z << 5], v15 = y2b[i3.w << 5];

        if (it < 3) {
            const size_t noden = boff + nbase + r + 8;
            cur_deg = g_deg[noden];
            const int4* nb4n = (const int4*)(g_nbr + noden*MAXDEG);
            i0 = nb4n[0]; i1 = nb4n[1]; i2 = nb4n[2]; i3 = nb4n[3];
        }

        a0 += self0(v0,  0 < deg);  a1 += self0(v1,  1 < deg);
        a2 += self0(v2,  2 < deg);  a3 += self0(v3,  3 < deg);
        a0 += self0(v4,  4 < deg);  a1 += self0(v5,  5 < deg);
        a2 += self0(v6,  6 < deg);  a3 += self0(v7,  7 < deg);
        a0 += self0(v8,  8 < deg);  a1 += self0(v9,  9 < deg);
        a2 += self0(v10, 10 < deg); a3 += self0(v11, 11 < deg);
        a0 += self0(v12, 12 < deg); a1 += self0(v13, 13 < deg);
        a2 += self0(v14, 14 < deg); a3 += self0(v15, 15 < deg);

        for (int k = 16; k < deg; ++k)
            a0 += y2b[nb[k] << 5];

        Zs[r*36 + l] = fmaxf(((a0 + a1) + (a2 + a3)) + bl, 0.f);
    }
    __syncthreads();

    const int tc = tid & 15, tr = tid >> 4;
    const int n0 = tr * 2;

    u64 acc[2][2];
    #pragma unroll
    for (int cc = 0; cc < 2; ++cc) {
        u64 ini = pack2(b2b[tc + 16*cc], 0.f);
        acc[0][cc] = ini; acc[1][cc] = ini;
    }
    #pragma unroll
    for (int f = 0; f < 32; f += 4) {
        ulonglong2 z0 = *(const ulonglong2*)(Zs + (n0+0)*36 + f);
        ulonglong2 z1 = *(const ulonglong2*)(Zs + (n0+1)*36 + f);
        const float* wb = W2q + (f >> 2)*128;
        ulonglong2 w0 = *(const ulonglong2*)(wb + (tc     )*4);
        ulonglong2 w1 = *(const ulonglong2*)(wb + (tc + 16)*4);
        ffma2(acc[0][0], z0.x, w0.x); ffma2(acc[0][0], z0.y, w0.y);
        ffma2(acc[0][1], z0.x, w1.x); ffma2(acc[0][1], z0.y, w1.y);
        ffma2(acc[1][0], z1.x, w0.x); ffma2(acc[1][0], z1.y, w0.y);
        ffma2(acc[1][1], z1.x, w1.x); ffma2(acc[1][1], z1.y, w1.y);
    }
    #pragma unroll
    for (int r = 0; r < 2; ++r) {
        const float m = msk[n0 + r];
        Hs[(n0+r)*33 + tc     ] = hsum2(acc[r][0]) * m;
        Hs[(n0+r)*33 + tc + 16] = hsum2(acc[r][1]) * m;
    }
    __syncthreads();

    if (tid < HID2) {
        float mx = Hs[tid];
        #pragma unroll 8
        for (int n = 1; n < 32; ++n) mx = fmaxf(mx, Hs[n*33 + tid]);
        g_bmax[(b*NBLK2 + blk)*HID2 + tid] = mx;
    }

    __threadfence();
    __syncthreads();
    if (tid == 0) {
        unsigned p = atomicAdd(&g_ctr, 1);
        sLast = (p == gridDim.x - 1);
    }
    __syncthreads();
    if (!sLast) return;
    __threadfence();

    __shared__ float gm[BATCH * HID2];
    for (int it = tid; it < BATCH*HID2; it += 256) {
        const int g = it >> 5, f = it & 31;
        float mx = g_bmax[(g*NBLK2)*HID2 + f];
        #pragma unroll
        for (int k = 1; k < NBLK2; ++k)
            mx = fmaxf(mx, g_bmax[(g*NBLK2 + k)*HID2 + f]);
        gm[it] = mx;
    }
    __syncthreads();
    for (int it = tid; it < BATCH*OUTD; it += 256) {
        const int g = it / OUTD, o = it % OUTD;
        float s = bfc[o];
        #pragma unroll
        for (int c = 0; c < HID2; ++c)
            s += gm[g*HID2 + c] * Wfc[c*OUTD + o];
        out[g*OUTD + o] = s;
    }
    if (tid == 0) g_ctr = 0;
}

// ---------------- launch (fork/join: ygemm overlaps scan) ----------------
extern "C" void kernel_launch(void* const* d_in, const int* in_sizes, int n_in,
                              void* d_out, int out_size)
{
    const float* x    = (const float*)d_in[0];
    const float* adj  = (const float*)d_in[1];
    const float* mask = (const float*)d_in[2];
    const float* W1a  = (const float*)d_in[3];
    const float* b1a  = (const float*)d_in[4];
    const float* W2a  = (const float*)d_in[5];
    const float* b2a  = (const float*)d_in[6];
    const float* W1b  = (const float*)d_in[7];
    const float* b1b  = (const float*)d_in[8];
    const float* W2b  = (const float*)d_in[9];
    const float* b2b  = (const float*)d_in[10];
    const float* Wfc  = (const float*)d_in[11];
    const float* bfc  = (const float*)d_in[12];
    float* out = (float*)d_out;

    // lazily created on the first (uncaptured) correctness call; reused during capture
    static cudaStream_t s_side = nullptr;
    static cudaEvent_t  e_fork = nullptr, e_join = nullptr;
    if (s_side == nullptr) {
        cudaStreamCreateWithFlags(&s_side, cudaStreamNonBlocking);
        cudaEventCreateWithFlags(&e_fork, cudaEventDisableTiming);
        cudaEventCreateWithFlags(&e_join, cudaEventDisableTiming);
        cudaFuncSetAttribute(gin_ygemm,  cudaFuncAttributeMaxDynamicSharedMemorySize, YG_SMEM);
        cudaFuncSetAttribute(gin_layer1, cudaFuncAttributeMaxDynamicSharedMemorySize, L1_SMEM);
    }

    // fork: side stream runs ygemm concurrently with scan on the main stream
    cudaEventRecord(e_fork, 0);
    cudaStreamWaitEvent(s_side, e_fork, 0);
    gin_ygemm<<<(BATCH*NNODE)/64, 256, YG_SMEM, s_side>>>(x, W1a);
    cudaEventRecord(e_join, s_side);

    gin_scan<<<BATCH*(NNODE/SROWS), 256>>>(adj);

    // join: layer1 needs both scan (lists) and ygemm (Y1)
    cudaStreamWaitEvent(0, e_join, 0);
    gin_layer1<<<BATCH*NBLK2, 256, L1_SMEM>>>(mask, b1a, W2a, b2a, W1b);
    gin_layer2out<<<BATCH*NBLK2, 256>>>(mask, b1b, W2b, b2b, Wfc, bfc, out);
}